// round 13
// baseline (speedup 1.0000x reference)
#include <cuda_runtime.h>
#include <cuda_bf16.h>

// CompositeValueNoise, spatially-binned v11.
// vs R12 (best, 94.7us): (1) zero_hist kernel ELIMINATED — __device__ globals
// are zero-init at load, and the main kernel (which never reads g_hist)
// re-zeroes g_hist/g_counter at its tail, so the "hist is zero" invariant is
// self-restoring across graph replays. (2) streaming reads use __ldcs so the
// x / g_sorted streams don't evict grid lines from L1/L2.

#define N_FIELDS 4
#define MAXN 2000000
#define BBITS 6
#define BDIM (1 << BBITS)            // 64
#define NBUCK (BDIM * BDIM * BDIM)   // 262144
#define SCAN_BLKS (NBUCK / 1024)     // 256

__device__ int    g_hist[NBUCK];     // zero at load; re-zeroed by main kernel
__device__ int    g_counter;
__device__ float4 g_sorted[MAXN];

__device__ __forceinline__ int cell_key(float px, float py, float pz) {
    int ci = min(max((int)(px * (float)BDIM), 0), BDIM - 1);
    int cj = min(max((int)(py * (float)BDIM), 0), BDIM - 1);
    int ck = min(max((int)(pz * (float)BDIM), 0), BDIM - 1);
    return (ci << (2 * BBITS)) | (cj << BBITS) | ck;   // k innermost
}

__global__ void hist_kernel(const float* __restrict__ x, int n) {
    int t = blockIdx.x * blockDim.x + threadIdx.x;
    int p0 = t * 4;
    if (p0 >= n) return;
    if (p0 + 4 <= n) {
        const float4* xv = reinterpret_cast<const float4*>(x) + 3 * (size_t)t;
        float4 a = __ldcs(xv + 0), b = __ldcs(xv + 1), c = __ldcs(xv + 2);
        atomicAdd(&g_hist[cell_key(a.x, a.y, a.z)], 1);
        atomicAdd(&g_hist[cell_key(a.w, b.x, b.y)], 1);
        atomicAdd(&g_hist[cell_key(b.z, b.w, c.x)], 1);
        atomicAdd(&g_hist[cell_key(c.y, c.z, c.w)], 1);
    } else {
        for (int p = p0; p < n; ++p)
            atomicAdd(&g_hist[cell_key(x[3*p], x[3*p+1], x[3*p+2])], 1);
    }
}

// Coalesced block scan of 1024 ints; block takes its global segment base via
// one early atomicAdd on g_counter, folded into the stored prefixes, so
// g_hist ends holding ABSOLUTE exclusive bucket bases. Segment order is
// run-arbitrary; each point's slot and value are unchanged -> deterministic.
__global__ void scan1_kernel() {
    __shared__ int warp_sums[8];
    __shared__ int s_base;
    int b = blockIdx.x, t = threadIdx.x;
    int lane = t & 31, wid = t >> 5;
    int base = b * 1024 + t * 4;

    int4 v = *reinterpret_cast<int4*>(&g_hist[base]);
    int tot = v.x + v.y + v.z + v.w;

    int inc = tot;
    #pragma unroll
    for (int o = 1; o < 32; o <<= 1) {
        int u = __shfl_up_sync(0xffffffffu, inc, o);
        if (lane >= o) inc += u;
    }
    if (lane == 31) warp_sums[wid] = inc;
    __syncthreads();
    if (wid == 0 && lane < 8) {
        int w = warp_sums[lane];
        #pragma unroll
        for (int o = 1; o < 8; o <<= 1) {
            int u = __shfl_up_sync(0xffu, w, o);
            if (lane >= o) w += u;
        }
        warp_sums[lane] = w;
        if (lane == 7) s_base = atomicAdd(&g_counter, w);  // w == block total
    }
    __syncthreads();
    int excl = s_base + (wid ? warp_sums[wid - 1] : 0) + inc - tot;

    int4 r;
    r.x = excl;
    r.y = excl + v.x;
    r.z = excl + v.x + v.y;
    r.w = excl + v.x + v.y + v.z;
    *reinterpret_cast<int4*>(&g_hist[base]) = r;
}

__device__ __forceinline__ void scatter_one(float px, float py, float pz, int i) {
    int pos = atomicAdd(&g_hist[cell_key(px, py, pz)], 1);
    __stcg(&g_sorted[pos], make_float4(px, py, pz, __int_as_float(i)));
}

__global__ void scatter_kernel(const float* __restrict__ x, int n) {
    int t = blockIdx.x * blockDim.x + threadIdx.x;
    int p0 = t * 4;
    if (p0 >= n) return;
    if (p0 + 4 <= n) {
        const float4* xv = reinterpret_cast<const float4*>(x) + 3 * (size_t)t;
        float4 a = __ldcs(xv + 0), b = __ldcs(xv + 1), c = __ldcs(xv + 2);
        scatter_one(a.x, a.y, a.z, p0 + 0);
        scatter_one(a.w, b.x, b.y, p0 + 1);
        scatter_one(b.z, b.w, c.x, p0 + 2);
        scatter_one(c.y, c.z, c.w, p0 + 3);
    } else {
        for (int p = p0; p < n; ++p)
            scatter_one(x[3*p], x[3*p+1], x[3*p+2], p);
    }
}

__device__ __forceinline__ float4 ld4(const float* __restrict__ p) {
    return __ldg(reinterpret_cast<const float4*>(p));
}

__device__ __forceinline__ float4 lerp4(float4 a, float4 b, float w) {
    float4 r;
    r.x = fmaf(w, b.x - a.x, a.x);
    r.y = fmaf(w, b.y - a.y, a.y);
    r.z = fmaf(w, b.z - a.z, a.z);
    r.w = fmaf(w, b.w - a.w, a.w);
    return r;
}

struct Lv {
    const float* base;
    int s0, s1;
    float wx, wy, wz;
};

__device__ __forceinline__ Lv prep(const float* __restrict__ V, int res,
                                   float px, float py, float pz) {
    const float resf = (float)res;
    float xs = px * resf, ys = py * resf, zs = pz * resf;
    float fx = floorf(xs), fy = floorf(ys), fz = floorf(zs);
    float tx = xs - fx,    ty = ys - fy,    tz = zs - fz;
    int i0 = (int)fx, j0 = (int)fy, k0 = (int)fz;
    Lv L;
    L.wx = (3.0f - 2.0f * tx) * tx * tx;
    L.wy = (3.0f - 2.0f * ty) * ty * ty;
    L.wz = (3.0f - 2.0f * tz) * tz * tz;
    const int r1 = res + 1;
    L.s1 = r1 * N_FIELDS;
    L.s0 = r1 * L.s1;
    L.base = V + (size_t)i0 * L.s0 + (size_t)j0 * L.s1 + (size_t)k0 * N_FIELDS;
    return L;
}

__device__ __forceinline__ void do_loads8(const Lv& L, float4 v[8]) {
    v[0] = ld4(L.base);
    v[1] = ld4(L.base + N_FIELDS);
    v[2] = ld4(L.base + L.s1);
    v[3] = ld4(L.base + L.s1 + N_FIELDS);
    v[4] = ld4(L.base + L.s0);
    v[5] = ld4(L.base + L.s0 + N_FIELDS);
    v[6] = ld4(L.base + L.s0 + L.s1);
    v[7] = ld4(L.base + L.s0 + L.s1 + N_FIELDS);
}

__device__ __forceinline__ float4 interp8(const Lv& L, const float4 v[8]) {
    // reference order: dim0 (wx), dim1 (wy), dim2 (wz)
    float4 a00 = lerp4(v[0], v[4], L.wx);
    float4 a01 = lerp4(v[1], v[5], L.wx);
    float4 a10 = lerp4(v[2], v[6], L.wx);
    float4 a11 = lerp4(v[3], v[7], L.wx);
    float4 b0 = lerp4(a00, a10, L.wy);
    float4 b1 = lerp4(a01, a11, L.wy);
    return lerp4(b0, b1, L.wz);
}

__global__ void __launch_bounds__(128) composite_value_noise_kernel(
    const float* __restrict__ V16,
    const float* __restrict__ V32,
    const float* __restrict__ V64,
    const float* __restrict__ V128,
    float* __restrict__ out,
    int n)
{
    int p = blockIdx.x * blockDim.x + threadIdx.x;

    if (p < n) {
        float4 pt = __ldcs(&g_sorted[p]);
        const float px = pt.x, py = pt.y, pz = pt.z;
        const int   idx = __float_as_int(pt.w);

        // Pair 1: V16 + V32 — 16 loads issued before interpolation math.
        Lv l0 = prep(V16, 16, px, py, pz);
        Lv l1 = prep(V32, 32, px, py, pz);
        float4 va[8], vb[8];
        do_loads8(l0, va);
        do_loads8(l1, vb);
        float4 n0 = interp8(l0, va);
        float4 n1 = interp8(l1, vb);

        // Pair 2: V64 + V128.
        Lv l2 = prep(V64, 64, px, py, pz);
        Lv l3 = prep(V128, 128, px, py, pz);
        do_loads8(l2, va);
        do_loads8(l3, vb);
        float4 n2 = interp8(l2, va);
        float4 n3 = interp8(l3, vb);

        float4 acc;
        acc.x = fmaf(0.125f, n3.x, fmaf(0.25f, n2.x, fmaf(0.5f, n1.x, n0.x)));
        acc.y = fmaf(0.125f, n3.y, fmaf(0.25f, n2.y, fmaf(0.5f, n1.y, n0.y)));
        acc.z = fmaf(0.125f, n3.z, fmaf(0.25f, n2.z, fmaf(0.5f, n1.z, n0.z)));
        acc.w = fmaf(0.125f, n3.w, fmaf(0.25f, n2.w, fmaf(0.5f, n1.w, n0.w)));

        __stcg(reinterpret_cast<float4*>(out) + idx, acc);
    }

    // Tail: restore the "g_hist is zero" invariant for the next invocation
    // (main kernel never reads g_hist, so this is safe within this launch).
    int z = blockIdx.x * blockDim.x + threadIdx.x;
    if (z < NBUCK / 4)
        __stcg(reinterpret_cast<int4*>(g_hist) + z, make_int4(0, 0, 0, 0));
    if (z == 0) g_counter = 0;
}

extern "C" void kernel_launch(void* const* d_in, const int* in_sizes, int n_in,
                              void* d_out, int out_size) {
    const float* x    = (const float*)d_in[0];
    const float* V16  = (const float*)d_in[1];
    const float* V32  = (const float*)d_in[2];
    const float* V64  = (const float*)d_in[3];
    const float* V128 = (const float*)d_in[4];
    float* out = (float*)d_out;

    int n = in_sizes[0] / 3;
    const int T = 256;
    int nquads = (n + 3) / 4;

    hist_kernel<<<(nquads + T - 1) / T, T>>>(x, n);
    scan1_kernel<<<SCAN_BLKS, 256>>>();
    scatter_kernel<<<(nquads + T - 1) / T, T>>>(x, n);

    const int TM = 128;
    int blocks = (n + TM - 1) / TM;
    composite_value_noise_kernel<<<blocks, TM>>>(V16, V32, V64, V128, out, n);
}

// round 14
// speedup vs baseline: 1.0099x; 1.0099x over previous
#include <cuda_runtime.h>
#include <cuda_bf16.h>

// CompositeValueNoise, spatially-binned v12.
// vs R13: (1) main kernel __launch_bounds__(128, 12) — force >=48 resident
// warps (R13 profile: occ 55.4%, L1 77% -> latency-exposed at regs=44).
// (2) floorf dropped (x>=0 so trunc==floor), trimming issue-side work.
// Pipeline otherwise identical: hist -> scan (early-atomic absolute bases) ->
// atomic scatter -> main (which re-zeroes g_hist at its tail).

#define N_FIELDS 4
#define MAXN 2000000
#define BBITS 6
#define BDIM (1 << BBITS)            // 64
#define NBUCK (BDIM * BDIM * BDIM)   // 262144
#define SCAN_BLKS (NBUCK / 1024)     // 256

__device__ int    g_hist[NBUCK];     // zero at load; re-zeroed by main kernel
__device__ int    g_counter;
__device__ float4 g_sorted[MAXN];

__device__ __forceinline__ int cell_key(float px, float py, float pz) {
    int ci = min(max((int)(px * (float)BDIM), 0), BDIM - 1);
    int cj = min(max((int)(py * (float)BDIM), 0), BDIM - 1);
    int ck = min(max((int)(pz * (float)BDIM), 0), BDIM - 1);
    return (ci << (2 * BBITS)) | (cj << BBITS) | ck;   // k innermost
}

__global__ void hist_kernel(const float* __restrict__ x, int n) {
    int t = blockIdx.x * blockDim.x + threadIdx.x;
    int p0 = t * 4;
    if (p0 >= n) return;
    if (p0 + 4 <= n) {
        const float4* xv = reinterpret_cast<const float4*>(x) + 3 * (size_t)t;
        float4 a = __ldcs(xv + 0), b = __ldcs(xv + 1), c = __ldcs(xv + 2);
        atomicAdd(&g_hist[cell_key(a.x, a.y, a.z)], 1);
        atomicAdd(&g_hist[cell_key(a.w, b.x, b.y)], 1);
        atomicAdd(&g_hist[cell_key(b.z, b.w, c.x)], 1);
        atomicAdd(&g_hist[cell_key(c.y, c.z, c.w)], 1);
    } else {
        for (int p = p0; p < n; ++p)
            atomicAdd(&g_hist[cell_key(x[3*p], x[3*p+1], x[3*p+2])], 1);
    }
}

// Coalesced block scan of 1024 ints; block takes its global segment base via
// one early atomicAdd on g_counter, folded into the stored prefixes, so
// g_hist ends holding ABSOLUTE exclusive bucket bases. Segment order is
// run-arbitrary; each point's slot and value are unchanged -> deterministic.
__global__ void scan1_kernel() {
    __shared__ int warp_sums[8];
    __shared__ int s_base;
    int b = blockIdx.x, t = threadIdx.x;
    int lane = t & 31, wid = t >> 5;
    int base = b * 1024 + t * 4;

    int4 v = *reinterpret_cast<int4*>(&g_hist[base]);
    int tot = v.x + v.y + v.z + v.w;

    int inc = tot;
    #pragma unroll
    for (int o = 1; o < 32; o <<= 1) {
        int u = __shfl_up_sync(0xffffffffu, inc, o);
        if (lane >= o) inc += u;
    }
    if (lane == 31) warp_sums[wid] = inc;
    __syncthreads();
    if (wid == 0 && lane < 8) {
        int w = warp_sums[lane];
        #pragma unroll
        for (int o = 1; o < 8; o <<= 1) {
            int u = __shfl_up_sync(0xffu, w, o);
            if (lane >= o) w += u;
        }
        warp_sums[lane] = w;
        if (lane == 7) s_base = atomicAdd(&g_counter, w);  // w == block total
    }
    __syncthreads();
    int excl = s_base + (wid ? warp_sums[wid - 1] : 0) + inc - tot;

    int4 r;
    r.x = excl;
    r.y = excl + v.x;
    r.z = excl + v.x + v.y;
    r.w = excl + v.x + v.y + v.z;
    *reinterpret_cast<int4*>(&g_hist[base]) = r;
}

__device__ __forceinline__ void scatter_one(float px, float py, float pz, int i) {
    int pos = atomicAdd(&g_hist[cell_key(px, py, pz)], 1);
    __stcg(&g_sorted[pos], make_float4(px, py, pz, __int_as_float(i)));
}

__global__ void scatter_kernel(const float* __restrict__ x, int n) {
    int t = blockIdx.x * blockDim.x + threadIdx.x;
    int p0 = t * 4;
    if (p0 >= n) return;
    if (p0 + 4 <= n) {
        const float4* xv = reinterpret_cast<const float4*>(x) + 3 * (size_t)t;
        float4 a = __ldcs(xv + 0), b = __ldcs(xv + 1), c = __ldcs(xv + 2);
        scatter_one(a.x, a.y, a.z, p0 + 0);
        scatter_one(a.w, b.x, b.y, p0 + 1);
        scatter_one(b.z, b.w, c.x, p0 + 2);
        scatter_one(c.y, c.z, c.w, p0 + 3);
    } else {
        for (int p = p0; p < n; ++p)
            scatter_one(x[3*p], x[3*p+1], x[3*p+2], p);
    }
}

__device__ __forceinline__ float4 ld4(const float* __restrict__ p) {
    return __ldg(reinterpret_cast<const float4*>(p));
}

__device__ __forceinline__ float4 lerp4(float4 a, float4 b, float w) {
    float4 r;
    r.x = fmaf(w, b.x - a.x, a.x);
    r.y = fmaf(w, b.y - a.y, a.y);
    r.z = fmaf(w, b.z - a.z, a.z);
    r.w = fmaf(w, b.w - a.w, a.w);
    return r;
}

struct Lv {
    const float* base;
    int s0, s1;
    float wx, wy, wz;
};

__device__ __forceinline__ Lv prep(const float* __restrict__ V, int res,
                                   float px, float py, float pz) {
    const float resf = (float)res;
    float xs = px * resf, ys = py * resf, zs = pz * resf;
    // x in [0,1) and xs >= 0: trunc == floor, no floorf needed.
    int i0 = (int)xs, j0 = (int)ys, k0 = (int)zs;
    float tx = xs - (float)i0, ty = ys - (float)j0, tz = zs - (float)k0;
    Lv L;
    L.wx = (3.0f - 2.0f * tx) * tx * tx;
    L.wy = (3.0f - 2.0f * ty) * ty * ty;
    L.wz = (3.0f - 2.0f * tz) * tz * tz;
    const int r1 = res + 1;
    L.s1 = r1 * N_FIELDS;
    L.s0 = r1 * L.s1;
    L.base = V + (size_t)i0 * L.s0 + (size_t)j0 * L.s1 + (size_t)k0 * N_FIELDS;
    return L;
}

__device__ __forceinline__ void do_loads8(const Lv& L, float4 v[8]) {
    v[0] = ld4(L.base);
    v[1] = ld4(L.base + N_FIELDS);
    v[2] = ld4(L.base + L.s1);
    v[3] = ld4(L.base + L.s1 + N_FIELDS);
    v[4] = ld4(L.base + L.s0);
    v[5] = ld4(L.base + L.s0 + N_FIELDS);
    v[6] = ld4(L.base + L.s0 + L.s1);
    v[7] = ld4(L.base + L.s0 + L.s1 + N_FIELDS);
}

__device__ __forceinline__ float4 interp8(const Lv& L, const float4 v[8]) {
    // reference order: dim0 (wx), dim1 (wy), dim2 (wz)
    float4 a00 = lerp4(v[0], v[4], L.wx);
    float4 a01 = lerp4(v[1], v[5], L.wx);
    float4 a10 = lerp4(v[2], v[6], L.wx);
    float4 a11 = lerp4(v[3], v[7], L.wx);
    float4 b0 = lerp4(a00, a10, L.wy);
    float4 b1 = lerp4(a01, a11, L.wy);
    return lerp4(b0, b1, L.wz);
}

__global__ void __launch_bounds__(128, 12) composite_value_noise_kernel(
    const float* __restrict__ V16,
    const float* __restrict__ V32,
    const float* __restrict__ V64,
    const float* __restrict__ V128,
    float* __restrict__ out,
    int n)
{
    int p = blockIdx.x * blockDim.x + threadIdx.x;

    if (p < n) {
        float4 pt = __ldcs(&g_sorted[p]);
        const float px = pt.x, py = pt.y, pz = pt.z;
        const int   idx = __float_as_int(pt.w);

        // Pair 1: V16 + V32 — 16 loads issued before interpolation math.
        Lv l0 = prep(V16, 16, px, py, pz);
        Lv l1 = prep(V32, 32, px, py, pz);
        float4 va[8], vb[8];
        do_loads8(l0, va);
        do_loads8(l1, vb);
        float4 n0 = interp8(l0, va);
        float4 n1 = interp8(l1, vb);

        // Pair 2: V64 + V128.
        Lv l2 = prep(V64, 64, px, py, pz);
        Lv l3 = prep(V128, 128, px, py, pz);
        do_loads8(l2, va);
        do_loads8(l3, vb);
        float4 n2 = interp8(l2, va);
        float4 n3 = interp8(l3, vb);

        float4 acc;
        acc.x = fmaf(0.125f, n3.x, fmaf(0.25f, n2.x, fmaf(0.5f, n1.x, n0.x)));
        acc.y = fmaf(0.125f, n3.y, fmaf(0.25f, n2.y, fmaf(0.5f, n1.y, n0.y)));
        acc.z = fmaf(0.125f, n3.z, fmaf(0.25f, n2.z, fmaf(0.5f, n1.z, n0.z)));
        acc.w = fmaf(0.125f, n3.w, fmaf(0.25f, n2.w, fmaf(0.5f, n1.w, n0.w)));

        __stcg(reinterpret_cast<float4*>(out) + idx, acc);
    }

    // Tail: restore the "g_hist is zero" invariant for the next invocation
    // (main kernel never reads g_hist, so this is safe within this launch).
    int z = blockIdx.x * blockDim.x + threadIdx.x;
    if (z < NBUCK / 4)
        __stcg(reinterpret_cast<int4*>(g_hist) + z, make_int4(0, 0, 0, 0));
    if (z == 0) g_counter = 0;
}

extern "C" void kernel_launch(void* const* d_in, const int* in_sizes, int n_in,
                              void* d_out, int out_size) {
    const float* x    = (const float*)d_in[0];
    const float* V16  = (const float*)d_in[1];
    const float* V32  = (const float*)d_in[2];
    const float* V64  = (const float*)d_in[3];
    const float* V128 = (const float*)d_in[4];
    float* out = (float*)d_out;

    int n = in_sizes[0] / 3;
    const int T = 256;
    int nquads = (n + 3) / 4;

    hist_kernel<<<(nquads + T - 1) / T, T>>>(x, n);
    scan1_kernel<<<SCAN_BLKS, 256>>>();
    scatter_kernel<<<(nquads + T - 1) / T, T>>>(x, n);

    const int TM = 128;
    int blocks = (n + TM - 1) / TM;
    composite_value_noise_kernel<<<blocks, TM>>>(V16, V32, V64, V128, out, n);
}